// round 3
// baseline (speedup 1.0000x reference)
#include <cuda_runtime.h>
#include <math.h>

// Problem constants
#define B_  2
#define T_  2048
#define C_  1024
#define H_  16
#define D_  64
#define BH_ (B_ * H_)       // 32
#define M_  (B_ * T_)       // 4096

// Scratch (device globals — no allocation allowed)
__device__ float g_q[BH_ * T_ * D_];     // [bh][t][d]  16 MB
__device__ float g_k[BH_ * T_ * D_];     // 16 MB
__device__ float g_v[BH_ * T_ * D_];     // 16 MB
__device__ float g_ctx[M_ * C_];         // [b*t][h*64+d] 16 MB

// ---------------------------------------------------------------------------
// GEMM 1: qkv = x @ W_qkv + b_qkv, scatter into Q/K/V [bh][t][d]
// M=4096, N=3072, K=1024. 128x128x8 tile, 256 threads, 8x8 microtile.
// ---------------------------------------------------------------------------
__global__ __launch_bounds__(256) void qkv_gemm(const float* __restrict__ x,
                                                const float* __restrict__ W,
                                                const float* __restrict__ bias) {
    __shared__ float As[8][128];   // A transposed: [k][m]
    __shared__ float Bs[8][128];   // [k][n]
    const int tid = threadIdx.x;
    const int bm = blockIdx.y * 128;
    const int bn = blockIdx.x * 128;
    const int N = 3 * C_;

    const int a_row = tid >> 1, a_col = (tid & 1) * 4;   // 128 rows x 8 cols
    const int b_row = tid >> 5, b_col = (tid & 31) * 4;  // 8 rows x 128 cols
    const int ty = tid >> 4, tx = tid & 15;

    float acc[8][8];
#pragma unroll
    for (int i = 0; i < 8; i++)
#pragma unroll
        for (int j = 0; j < 8; j++) acc[i][j] = 0.f;

    const float* Ap = x + (bm + a_row) * C_ + a_col;
    const float* Bp = W + b_row * N + bn + b_col;

    for (int k0 = 0; k0 < C_; k0 += 8) {
        float4 av = *(const float4*)(Ap + k0);
        float4 bv = *(const float4*)(Bp + (size_t)k0 * N);
        As[a_col + 0][a_row] = av.x;
        As[a_col + 1][a_row] = av.y;
        As[a_col + 2][a_row] = av.z;
        As[a_col + 3][a_row] = av.w;
        *(float4*)&Bs[b_row][b_col] = bv;
        __syncthreads();
#pragma unroll
        for (int k = 0; k < 8; k++) {
            float a[8], b[8];
            // split microtile (tx*4, 64+tx*4): contiguous 16B per lane -> conflict-free LDS.128
            *(float4*)(a)     = *(const float4*)&As[k][ty * 4];
            *(float4*)(a + 4) = *(const float4*)&As[k][64 + ty * 4];
            *(float4*)(b)     = *(const float4*)&Bs[k][tx * 4];
            *(float4*)(b + 4) = *(const float4*)&Bs[k][64 + tx * 4];
#pragma unroll
            for (int i = 0; i < 8; i++)
#pragma unroll
                for (int j = 0; j < 8; j++)
                    acc[i][j] = fmaf(a[i], b[j], acc[i][j]);
        }
        __syncthreads();
    }

    // Epilogue: add bias, scatter n -> (which, h, d), m -> (b, t)
#pragma unroll
    for (int i = 0; i < 8; i++) {
        int m = bm + ((i < 4) ? (ty * 4 + i) : (64 + ty * 4 + (i - 4)));
        int bidx = m >> 11, t = m & (T_ - 1);
#pragma unroll
        for (int j = 0; j < 8; j++) {
            int n = bn + ((j < 4) ? (tx * 4 + j) : (64 + tx * 4 + (j - 4)));
            float v = acc[i][j] + bias[n];
            int which = n >> 10;
            int rem = n & 1023;
            int h = rem >> 6, d = rem & 63;
            float* dst = (which == 0) ? g_q : (which == 1) ? g_k : g_v;
            dst[(((bidx << 4) + h) * T_ + t) * D_ + d] = v;
        }
    }
}

// ---------------------------------------------------------------------------
// GEMM 2: out = ctx @ W_out + b_out. M=4096, N=1024, K=1024.
// ---------------------------------------------------------------------------
__global__ __launch_bounds__(256) void out_gemm(const float* __restrict__ W,
                                                const float* __restrict__ bias,
                                                float* __restrict__ out) {
    __shared__ float As[8][128];
    __shared__ float Bs[8][128];
    const int tid = threadIdx.x;
    const int bm = blockIdx.y * 128;
    const int bn = blockIdx.x * 128;
    const int N = C_;

    const int a_row = tid >> 1, a_col = (tid & 1) * 4;
    const int b_row = tid >> 5, b_col = (tid & 31) * 4;
    const int ty = tid >> 4, tx = tid & 15;

    float acc[8][8];
#pragma unroll
    for (int i = 0; i < 8; i++)
#pragma unroll
        for (int j = 0; j < 8; j++) acc[i][j] = 0.f;

    const float* Ap = g_ctx + (bm + a_row) * C_ + a_col;
    const float* Bp = W + b_row * N + bn + b_col;

    for (int k0 = 0; k0 < C_; k0 += 8) {
        float4 av = *(const float4*)(Ap + k0);
        float4 bv = *(const float4*)(Bp + (size_t)k0 * N);
        As[a_col + 0][a_row] = av.x;
        As[a_col + 1][a_row] = av.y;
        As[a_col + 2][a_row] = av.z;
        As[a_col + 3][a_row] = av.w;
        *(float4*)&Bs[b_row][b_col] = bv;
        __syncthreads();
#pragma unroll
        for (int k = 0; k < 8; k++) {
            float a[8], b[8];
            *(float4*)(a)     = *(const float4*)&As[k][ty * 4];
            *(float4*)(a + 4) = *(const float4*)&As[k][64 + ty * 4];
            *(float4*)(b)     = *(const float4*)&Bs[k][tx * 4];
            *(float4*)(b + 4) = *(const float4*)&Bs[k][64 + tx * 4];
#pragma unroll
            for (int i = 0; i < 8; i++)
#pragma unroll
                for (int j = 0; j < 8; j++)
                    acc[i][j] = fmaf(a[i], b[j], acc[i][j]);
        }
        __syncthreads();
    }

#pragma unroll
    for (int i = 0; i < 8; i++) {
        int m = bm + ((i < 4) ? (ty * 4 + i) : (64 + ty * 4 + (i - 4)));
#pragma unroll
        for (int j = 0; j < 8; j++) {
            int n = bn + ((j < 4) ? (tx * 4 + j) : (64 + tx * 4 + (j - 4)));
            out[(size_t)m * C_ + n] = acc[i][j] + bias[n];
        }
    }
}

// ---------------------------------------------------------------------------
// Flash attention, fp32. Block = (bh, q-tile of 64). 256 threads (16x16),
// 4x4 microtile. Online softmax with 16-lane shuffle reductions.
//
// smem bank notes (32 banks, 4B):
//   Qs pad 65: read Qs[r][d] (r=ty*4+i): tx broadcast, 2 warp-rows -> banks
//              (r+d) differ by 4 -> conflict-free.
//   KV pad 65: K-read KV[c][d] (c=tx*4+j): bank (c+d) -> tx,tx+8 collide ->
//              2-way. V-read KV[s][c0+j]: bank (s+4tx+j) -> 2-way.
//   Ps pad 68: float4 stores aligned (68%4==0, row stride 272B = 17*16B);
//              read Ps[r][s]: tx broadcast, warp-rows 16 banks apart -> clean.
// ---------------------------------------------------------------------------
#define QKV_PAD 65
#define P_PAD   68
#define ATTN_SMEM_FLOATS (2 * 64 * QKV_PAD + 64 * P_PAD)
#define ATTN_SMEM_BYTES  (ATTN_SMEM_FLOATS * 4)   // 50688 B -> needs opt-in

__device__ __forceinline__ float red_max16(float v) {
    v = fmaxf(v, __shfl_xor_sync(0xffffffffu, v, 1));
    v = fmaxf(v, __shfl_xor_sync(0xffffffffu, v, 2));
    v = fmaxf(v, __shfl_xor_sync(0xffffffffu, v, 4));
    v = fmaxf(v, __shfl_xor_sync(0xffffffffu, v, 8));
    return v;
}
__device__ __forceinline__ float red_sum16(float v) {
    v += __shfl_xor_sync(0xffffffffu, v, 1);
    v += __shfl_xor_sync(0xffffffffu, v, 2);
    v += __shfl_xor_sync(0xffffffffu, v, 4);
    v += __shfl_xor_sync(0xffffffffu, v, 8);
    return v;
}

__global__ __launch_bounds__(256) void attn_kernel() {
    extern __shared__ float sm[];
    float* Qs = sm;                       // [64][65]
    float* KV = sm + 64 * QKV_PAD;        // [64][65]  (K tile, then V tile)
    float* Ps = sm + 2 * 64 * QKV_PAD;    // [64][68]

    const int tid = threadIdx.x;
    const int ty = tid >> 4, tx = tid & 15;
    const int bh = blockIdx.y;
    const int q0 = blockIdx.x * 64;

    const float* Qg = g_q + (size_t)bh * T_ * D_;
    const float* Kg = g_k + (size_t)bh * T_ * D_;
    const float* Vg = g_v + (size_t)bh * T_ * D_;

    // Load Q tile [64][64] (coalesced LDG.128, scalar STS into padded rows)
    for (int v = tid; v < 64 * 16; v += 256) {
        int row = v >> 4, d4 = (v & 15) * 4;
        float4 q4 = *(const float4*)(Qg + (q0 + row) * D_ + d4);
        float* dst = Qs + row * QKV_PAD + d4;
        dst[0] = q4.x; dst[1] = q4.y; dst[2] = q4.z; dst[3] = q4.w;
    }

    float m_i[4], l_i[4], o[4][4];
#pragma unroll
    for (int i = 0; i < 4; i++) {
        m_i[i] = -1e30f; l_i[i] = 0.f;
#pragma unroll
        for (int j = 0; j < 4; j++) o[i][j] = 0.f;
    }

    const int r0 = ty * 4;
    const int c0 = tx * 4;
    const float scale = 0.125f;   // 1/sqrt(64)

    for (int kt = 0; kt < T_; kt += 64) {
        __syncthreads();  // previous-iter KV/Ps consumers done; Q stores visible (iter 0)

        // Load K tile
        for (int v = tid; v < 64 * 16; v += 256) {
            int row = v >> 4, d4 = (v & 15) * 4;
            float4 k4 = *(const float4*)(Kg + (kt + row) * D_ + d4);
            float* dst = KV + row * QKV_PAD + d4;
            dst[0] = k4.x; dst[1] = k4.y; dst[2] = k4.z; dst[3] = k4.w;
        }
        __syncthreads();

        // S = Q K^T
        float s[4][4];
#pragma unroll
        for (int i = 0; i < 4; i++)
#pragma unroll
            for (int j = 0; j < 4; j++) s[i][j] = 0.f;

#pragma unroll 8
        for (int d = 0; d < 64; d++) {
            float a[4], b[4];
#pragma unroll
            for (int i = 0; i < 4; i++) a[i] = Qs[(r0 + i) * QKV_PAD + d];
#pragma unroll
            for (int j = 0; j < 4; j++) b[j] = KV[(c0 + j) * QKV_PAD + d];
#pragma unroll
            for (int i = 0; i < 4; i++)
#pragma unroll
                for (int j = 0; j < 4; j++)
                    s[i][j] = fmaf(a[i], b[j], s[i][j]);
        }

        // Online softmax per row (replicated across the 16 tx lanes)
#pragma unroll
        for (int i = 0; i < 4; i++) {
            float mx = s[i][0] * scale;
#pragma unroll
            for (int j = 1; j < 4; j++) mx = fmaxf(mx, s[i][j] * scale);
            mx = red_max16(mx);
            float mnew = fmaxf(m_i[i], mx);
            float p[4], psum = 0.f;
#pragma unroll
            for (int j = 0; j < 4; j++) {
                p[j] = __expf(s[i][j] * scale - mnew);
                psum += p[j];
            }
            psum = red_sum16(psum);
            float corr = __expf(m_i[i] - mnew);
            l_i[i] = l_i[i] * corr + psum;
            m_i[i] = mnew;
#pragma unroll
            for (int j = 0; j < 4; j++) o[i][j] *= corr;
            *(float4*)&Ps[(r0 + i) * P_PAD + c0] = make_float4(p[0], p[1], p[2], p[3]);
        }
        __syncthreads();  // Ps visible; K reads done

        // Load V tile (overwrites K buffer)
        for (int v = tid; v < 64 * 16; v += 256) {
            int row = v >> 4, d4 = (v & 15) * 4;
            float4 v4 = *(const float4*)(Vg + (kt + row) * D_ + d4);
            float* dst = KV + row * QKV_PAD + d4;
            dst[0] = v4.x; dst[1] = v4.y; dst[2] = v4.z; dst[3] = v4.w;
        }
        __syncthreads();

        // O += P @ V
#pragma unroll 8
        for (int sc = 0; sc < 64; sc++) {
            float a[4], b[4];
#pragma unroll
            for (int i = 0; i < 4; i++) a[i] = Ps[(r0 + i) * P_PAD + sc];
#pragma unroll
            for (int j = 0; j < 4; j++) b[j] = KV[sc * QKV_PAD + c0 + j];
#pragma unroll
            for (int i = 0; i < 4; i++)
#pragma unroll
                for (int j = 0; j < 4; j++)
                    o[i][j] = fmaf(a[i], b[j], o[i][j]);
        }
    }

    // Normalize and write ctx[b][t][h*64+d]
    const int bidx = bh >> 4, h = bh & 15;
#pragma unroll
    for (int i = 0; i < 4; i++) {
        float inv = 1.0f / l_i[i];
        int t = q0 + r0 + i;
        float* dst = g_ctx + (size_t)(bidx * T_ + t) * C_ + h * D_ + c0;
        float4 ov = make_float4(o[i][0] * inv, o[i][1] * inv, o[i][2] * inv, o[i][3] * inv);
        *(float4*)dst = ov;
    }
}

// ---------------------------------------------------------------------------
// Launch
// ---------------------------------------------------------------------------
extern "C" void kernel_launch(void* const* d_in, const int* in_sizes, int n_in,
                              void* d_out, int out_size) {
    const float* x     = (const float*)d_in[0];
    const float* W_qkv = (const float*)d_in[1];
    const float* b_qkv = (const float*)d_in[2];
    const float* W_out = (const float*)d_in[3];
    const float* b_out = (const float*)d_in[4];
    float* out = (float*)d_out;

    (void)in_sizes; (void)n_in; (void)out_size;

    // Opt-in for >48KB dynamic smem (cheap, deterministic, not a stream op)
    cudaFuncSetAttribute(attn_kernel, cudaFuncAttributeMaxDynamicSharedMemorySize,
                         ATTN_SMEM_BYTES);

    qkv_gemm<<<dim3(3 * C_ / 128, M_ / 128), 256>>>(x, W_qkv, b_qkv);
    attn_kernel<<<dim3(T_ / 64, BH_), 256, ATTN_SMEM_BYTES>>>();
    out_gemm<<<dim3(C_ / 128, M_ / 128), 256>>>(W_out, b_out, out);
}

// round 8
// speedup vs baseline: 1.5070x; 1.5070x over previous
#include <cuda_runtime.h>
#include <math.h>
#include <stdint.h>

// Problem constants
#define B_  2
#define T_  2048
#define C_  1024
#define H_  16
#define D_  64
#define BH_ (B_ * H_)       // 32
#define M_  (B_ * T_)       // 4096

// Scratch (device globals — no allocation allowed)
__device__ float g_q[BH_ * T_ * D_];     // [bh][t][d]
__device__ float g_k[BH_ * T_ * D_];
__device__ float g_v[BH_ * T_ * D_];
__device__ float g_ctx[M_ * C_];         // [b*t][h*64+d]

// ===========================================================================
// tf32 warp MMA helpers (sm_80+ baseline — valid on plain sm_103 target)
// ===========================================================================
__device__ __forceinline__ uint32_t f2tf32(float f) {
    uint32_t u;
    asm("cvt.rna.tf32.f32 %0, %1;" : "=r"(u) : "f"(f));
    return u;
}

__device__ __forceinline__ void mma_tf32(float* c, const uint32_t* a,
                                         const uint32_t* b) {
    asm volatile(
        "mma.sync.aligned.m16n8k8.row.col.f32.tf32.tf32.f32 "
        "{%0,%1,%2,%3}, {%4,%5,%6,%7}, {%8,%9}, {%0,%1,%2,%3};"
        : "+f"(c[0]), "+f"(c[1]), "+f"(c[2]), "+f"(c[3])
        : "r"(a[0]), "r"(a[1]), "r"(a[2]), "r"(a[3]), "r"(b[0]), "r"(b[1]));
}

// ===========================================================================
// tf32 mma.sync GEMM: C[M,N] = A[M,K=1024] @ B[K,N] + bias.
// CTA 128x128, 8 warps (2x4), warp tile 64x32, K-stage 32.
//
// smem bank analysis (32 banks, 4B words):
//   As[m][36] (m-major, k minor 0..31):
//     a0 read addr = 36m + t  (m = 16-mult + g) -> bank (4g + t) % 32:
//     g in 0..7, t in 0..3 -> all 32 lanes distinct. Conflict-free.
//     STS.128 per 8-lane phase: one m row, kk 0..7 -> 128B contiguous. Clean.
//   Bs[k][136] (k-major, n minor 0..127):
//     b0 read addr = 136(kb+t) + n (n = 8-mult + g) -> bank (8t + g) % 32:
//     all 32 lanes distinct. Conflict-free.
//     STS.128 per phase: same k, n4 0..7 -> words 4*n4 -> banks 0,4..28. Clean.
//
// MODE 0: A = x, scatter into g_q/g_k/g_v.  MODE 1: A = g_ctx, write Out.
// ===========================================================================
#define APAD 36
#define BPAD 136

template <int MODE>
__global__ __launch_bounds__(256, 2) void mma_gemm(const float* __restrict__ Ain,
                                                   const float* __restrict__ Bw,
                                                   const float* __restrict__ bias,
                                                   float* __restrict__ Out,
                                                   int N) {
    __shared__ uint32_t As[128 * APAD];   // [m][k]  18432 B
    __shared__ uint32_t Bs[32 * BPAD];    // [k][n]  17408 B

    const int tid = threadIdx.x;
    const int wid = tid >> 5, lane = tid & 31;
    const int warp_m = (wid >> 2) * 64;   // 0 / 64
    const int warp_n = (wid & 3) * 32;    // 0..96
    const int g = lane >> 2, t = lane & 3;
    const int bm = blockIdx.y * 128, bn = blockIdx.x * 128;

    const float* Ap = (MODE == 0) ? Ain : (const float*)g_ctx;

    float acc[4][4][4];
#pragma unroll
    for (int mf = 0; mf < 4; mf++)
#pragma unroll
        for (int nf = 0; nf < 4; nf++)
#pragma unroll
            for (int r = 0; r < 4; r++) acc[mf][nf][r] = 0.f;

    for (int k0 = 0; k0 < C_; k0 += 32) {
        __syncthreads();   // previous stage fully consumed

        // A tile: 128 rows x 32 k. Coalesced LDG.128 (8 lanes = one 128B row).
#pragma unroll
        for (int r = 0; r < 4; r++) {
            int idx = tid + r * 256;
            int m = idx >> 3, kk = idx & 7;
            float4 v = *(const float4*)(Ap + (size_t)(bm + m) * C_ + k0 + kk * 4);
            uint32_t* d = &As[m * APAD + kk * 4];
            d[0] = f2tf32(v.x); d[1] = f2tf32(v.y);
            d[2] = f2tf32(v.z); d[3] = f2tf32(v.w);
        }
        // B tile: 32 k-rows x 128 n. Coalesced (32 lanes = 512B of one k-row).
#pragma unroll
        for (int r = 0; r < 4; r++) {
            int idx = tid + r * 256;
            int k = idx >> 5, n4 = idx & 31;
            float4 v = *(const float4*)(Bw + (size_t)(k0 + k) * N + bn + n4 * 4);
            uint32_t* d = &Bs[k * BPAD + n4 * 4];
            d[0] = f2tf32(v.x); d[1] = f2tf32(v.y);
            d[2] = f2tf32(v.z); d[3] = f2tf32(v.w);
        }
        __syncthreads();

#pragma unroll
        for (int ks = 0; ks < 4; ks++) {
            const int kb = ks * 8;
            uint32_t af[4][4], bf[4][2];
#pragma unroll
            for (int mf = 0; mf < 4; mf++) {
                const uint32_t* ap = &As[(warp_m + mf * 16 + g) * APAD + kb + t];
                af[mf][0] = ap[0];
                af[mf][1] = ap[8 * APAD];
                af[mf][2] = ap[4];
                af[mf][3] = ap[8 * APAD + 4];
            }
#pragma unroll
            for (int nf = 0; nf < 4; nf++) {
                const uint32_t* bp = &Bs[(kb + t) * BPAD + warp_n + nf * 8 + g];
                bf[nf][0] = bp[0];
                bf[nf][1] = bp[4 * BPAD];
            }
#pragma unroll
            for (int mf = 0; mf < 4; mf++)
#pragma unroll
                for (int nf = 0; nf < 4; nf++)
                    mma_tf32(acc[mf][nf], af[mf], bf[nf]);
        }
    }

    // Epilogue: c0/c1 = (row g, cols 2t, 2t+1); c2/c3 = row g+8.
#pragma unroll
    for (int mf = 0; mf < 4; mf++) {
#pragma unroll
        for (int nf = 0; nf < 4; nf++) {
            const int n = bn + warp_n + nf * 8 + 2 * t;
            const float b0v = bias[n], b1v = bias[n + 1];
#pragma unroll
            for (int half = 0; half < 2; half++) {
                const int m = bm + warp_m + mf * 16 + g + half * 8;
                float v0 = acc[mf][nf][half * 2 + 0] + b0v;
                float v1 = acc[mf][nf][half * 2 + 1] + b1v;
                if (MODE == 0) {
                    int which = n >> 10;
                    int rem = n & 1023;
                    int h = rem >> 6, d = rem & 63;   // d even; pair in-head
                    int bi = m >> 11, tt = m & (T_ - 1);
                    float* dst = (which == 0) ? g_q : (which == 1) ? g_k : g_v;
                    *(float2*)&dst[(size_t)(((bi << 4) + h) * T_ + tt) * D_ + d] =
                        make_float2(v0, v1);
                } else {
                    *(float2*)&Out[(size_t)m * N + n] = make_float2(v0, v1);
                }
            }
        }
    }
}

// ===========================================================================
// Flash attention, fp32 SIMT (unchanged from passing R3 kernel).
// ===========================================================================
#define QKV_PAD 65
#define P_PAD   68
#define ATTN_SMEM_FLOATS (2 * 64 * QKV_PAD + 64 * P_PAD)
#define ATTN_SMEM_BYTES  (ATTN_SMEM_FLOATS * 4)

__device__ __forceinline__ float red_max16(float v) {
    v = fmaxf(v, __shfl_xor_sync(0xffffffffu, v, 1));
    v = fmaxf(v, __shfl_xor_sync(0xffffffffu, v, 2));
    v = fmaxf(v, __shfl_xor_sync(0xffffffffu, v, 4));
    v = fmaxf(v, __shfl_xor_sync(0xffffffffu, v, 8));
    return v;
}
__device__ __forceinline__ float red_sum16(float v) {
    v += __shfl_xor_sync(0xffffffffu, v, 1);
    v += __shfl_xor_sync(0xffffffffu, v, 2);
    v += __shfl_xor_sync(0xffffffffu, v, 4);
    v += __shfl_xor_sync(0xffffffffu, v, 8);
    return v;
}

__global__ __launch_bounds__(256) void attn_kernel() {
    extern __shared__ float sm[];
    float* Qs = sm;                       // [64][65]
    float* KV = sm + 64 * QKV_PAD;        // [64][65]
    float* Ps = sm + 2 * 64 * QKV_PAD;    // [64][68]

    const int tid = threadIdx.x;
    const int ty = tid >> 4, tx = tid & 15;
    const int bh = blockIdx.y;
    const int q0 = blockIdx.x * 64;

    const float* Qg = g_q + (size_t)bh * T_ * D_;
    const float* Kg = g_k + (size_t)bh * T_ * D_;
    const float* Vg = g_v + (size_t)bh * T_ * D_;

    for (int v = tid; v < 64 * 16; v += 256) {
        int row = v >> 4, d4 = (v & 15) * 4;
        float4 q4 = *(const float4*)(Qg + (q0 + row) * D_ + d4);
        float* dst = Qs + row * QKV_PAD + d4;
        dst[0] = q4.x; dst[1] = q4.y; dst[2] = q4.z; dst[3] = q4.w;
    }

    float m_i[4], l_i[4], o[4][4];
#pragma unroll
    for (int i = 0; i < 4; i++) {
        m_i[i] = -1e30f; l_i[i] = 0.f;
#pragma unroll
        for (int j = 0; j < 4; j++) o[i][j] = 0.f;
    }

    const int r0 = ty * 4;
    const int c0 = tx * 4;
    const float scale = 0.125f;

    for (int kt = 0; kt < T_; kt += 64) {
        __syncthreads();

        for (int v = tid; v < 64 * 16; v += 256) {
            int row = v >> 4, d4 = (v & 15) * 4;
            float4 k4 = *(const float4*)(Kg + (kt + row) * D_ + d4);
            float* dst = KV + row * QKV_PAD + d4;
            dst[0] = k4.x; dst[1] = k4.y; dst[2] = k4.z; dst[3] = k4.w;
        }
        __syncthreads();

        float s[4][4];
#pragma unroll
        for (int i = 0; i < 4; i++)
#pragma unroll
            for (int j = 0; j < 4; j++) s[i][j] = 0.f;

#pragma unroll 8
        for (int d = 0; d < 64; d++) {
            float a[4], b[4];
#pragma unroll
            for (int i = 0; i < 4; i++) a[i] = Qs[(r0 + i) * QKV_PAD + d];
#pragma unroll
            for (int j = 0; j < 4; j++) b[j] = KV[(c0 + j) * QKV_PAD + d];
#pragma unroll
            for (int i = 0; i < 4; i++)
#pragma unroll
                for (int j = 0; j < 4; j++)
                    s[i][j] = fmaf(a[i], b[j], s[i][j]);
        }

#pragma unroll
        for (int i = 0; i < 4; i++) {
            float mx = s[i][0] * scale;
#pragma unroll
            for (int j = 1; j < 4; j++) mx = fmaxf(mx, s[i][j] * scale);
            mx = red_max16(mx);
            float mnew = fmaxf(m_i[i], mx);
            float p[4], psum = 0.f;
#pragma unroll
            for (int j = 0; j < 4; j++) {
                p[j] = __expf(s[i][j] * scale - mnew);
                psum += p[j];
            }
            psum = red_sum16(psum);
            float corr = __expf(m_i[i] - mnew);
            l_i[i] = l_i[i] * corr + psum;
            m_i[i] = mnew;
#pragma unroll
            for (int j = 0; j < 4; j++) o[i][j] *= corr;
            *(float4*)&Ps[(r0 + i) * P_PAD + c0] = make_float4(p[0], p[1], p[2], p[3]);
        }
        __syncthreads();

        for (int v = tid; v < 64 * 16; v += 256) {
            int row = v >> 4, d4 = (v & 15) * 4;
            float4 v4 = *(const float4*)(Vg + (kt + row) * D_ + d4);
            float* dst = KV + row * QKV_PAD + d4;
            dst[0] = v4.x; dst[1] = v4.y; dst[2] = v4.z; dst[3] = v4.w;
        }
        __syncthreads();

#pragma unroll 8
        for (int sc = 0; sc < 64; sc++) {
            float a[4], b[4];
#pragma unroll
            for (int i = 0; i < 4; i++) a[i] = Ps[(r0 + i) * P_PAD + sc];
#pragma unroll
            for (int j = 0; j < 4; j++) b[j] = KV[sc * QKV_PAD + c0 + j];
#pragma unroll
            for (int i = 0; i < 4; i++)
#pragma unroll
                for (int j = 0; j < 4; j++)
                    o[i][j] = fmaf(a[i], b[j], o[i][j]);
        }
    }

    const int bidx = bh >> 4, h = bh & 15;
#pragma unroll
    for (int i = 0; i < 4; i++) {
        float inv = 1.0f / l_i[i];
        int t = q0 + r0 + i;
        float* dst = g_ctx + (size_t)(bidx * T_ + t) * C_ + h * D_ + c0;
        *(float4*)dst = make_float4(o[i][0] * inv, o[i][1] * inv,
                                    o[i][2] * inv, o[i][3] * inv);
    }
}

// ---------------------------------------------------------------------------
// Launch
// ---------------------------------------------------------------------------
extern "C" void kernel_launch(void* const* d_in, const int* in_sizes, int n_in,
                              void* d_out, int out_size) {
    const float* x     = (const float*)d_in[0];
    const float* W_qkv = (const float*)d_in[1];
    const float* b_qkv = (const float*)d_in[2];
    const float* W_out = (const float*)d_in[3];
    const float* b_out = (const float*)d_in[4];
    float* out = (float*)d_out;

    (void)in_sizes; (void)n_in; (void)out_size;

    cudaFuncSetAttribute(attn_kernel, cudaFuncAttributeMaxDynamicSharedMemorySize,
                         ATTN_SMEM_BYTES);

    mma_gemm<0><<<dim3(3 * C_ / 128, M_ / 128), 256>>>(x, W_qkv, b_qkv,
                                                       nullptr, 3 * C_);
    attn_kernel<<<dim3(T_ / 64, BH_), 256, ATTN_SMEM_BYTES>>>();
    mma_gemm<1><<<dim3(C_ / 128, M_ / 128), 256>>>(nullptr, W_out, b_out,
                                                   out, C_);
}

// round 10
// speedup vs baseline: 3.6951x; 2.4520x over previous
#include <cuda_runtime.h>
#include <math.h>
#include <stdint.h>

// Problem constants
#define B_  2
#define T_  2048
#define C_  1024
#define H_  16
#define D_  64
#define BH_ (B_ * H_)       // 32
#define M_  (B_ * T_)       // 4096

// Scratch (device globals — no allocation allowed)
__device__ float g_q[BH_ * T_ * D_];     // [bh][t][d]
__device__ float g_k[BH_ * T_ * D_];
__device__ float g_v[BH_ * T_ * D_];
__device__ float g_ctx[M_ * C_];         // [b*t][h*64+d]

// ===========================================================================
// tf32 warp MMA helpers (sm_80+ baseline — valid on plain sm_103 target)
// ===========================================================================
__device__ __forceinline__ uint32_t f2tf32(float f) {
    uint32_t u;
    asm("cvt.rna.tf32.f32 %0, %1;" : "=r"(u) : "f"(f));
    return u;
}

__device__ __forceinline__ void mma_tf32(float* c, const uint32_t* a,
                                         const uint32_t* b) {
    asm volatile(
        "mma.sync.aligned.m16n8k8.row.col.f32.tf32.tf32.f32 "
        "{%0,%1,%2,%3}, {%4,%5,%6,%7}, {%8,%9}, {%0,%1,%2,%3};"
        : "+f"(c[0]), "+f"(c[1]), "+f"(c[2]), "+f"(c[3])
        : "r"(a[0]), "r"(a[1]), "r"(a[2]), "r"(a[3]), "r"(b[0]), "r"(b[1]));
}

// ===========================================================================
// tf32 mma.sync GEMM (unchanged from passing R8): C = A @ B + bias.
// ===========================================================================
#define APAD 36
#define BPAD 136

template <int MODE>
__global__ __launch_bounds__(256, 2) void mma_gemm(const float* __restrict__ Ain,
                                                   const float* __restrict__ Bw,
                                                   const float* __restrict__ bias,
                                                   float* __restrict__ Out,
                                                   int N) {
    __shared__ uint32_t As[128 * APAD];   // [m][k]
    __shared__ uint32_t Bs[32 * BPAD];    // [k][n]

    const int tid = threadIdx.x;
    const int wid = tid >> 5, lane = tid & 31;
    const int warp_m = (wid >> 2) * 64;
    const int warp_n = (wid & 3) * 32;
    const int g = lane >> 2, t = lane & 3;
    const int bm = blockIdx.y * 128, bn = blockIdx.x * 128;

    const float* Ap = (MODE == 0) ? Ain : (const float*)g_ctx;

    float acc[4][4][4];
#pragma unroll
    for (int mf = 0; mf < 4; mf++)
#pragma unroll
        for (int nf = 0; nf < 4; nf++)
#pragma unroll
            for (int r = 0; r < 4; r++) acc[mf][nf][r] = 0.f;

    for (int k0 = 0; k0 < C_; k0 += 32) {
        __syncthreads();
#pragma unroll
        for (int r = 0; r < 4; r++) {
            int idx = tid + r * 256;
            int m = idx >> 3, kk = idx & 7;
            float4 v = *(const float4*)(Ap + (size_t)(bm + m) * C_ + k0 + kk * 4);
            uint32_t* d = &As[m * APAD + kk * 4];
            d[0] = f2tf32(v.x); d[1] = f2tf32(v.y);
            d[2] = f2tf32(v.z); d[3] = f2tf32(v.w);
        }
#pragma unroll
        for (int r = 0; r < 4; r++) {
            int idx = tid + r * 256;
            int k = idx >> 5, n4 = idx & 31;
            float4 v = *(const float4*)(Bw + (size_t)(k0 + k) * N + bn + n4 * 4);
            uint32_t* d = &Bs[k * BPAD + n4 * 4];
            d[0] = f2tf32(v.x); d[1] = f2tf32(v.y);
            d[2] = f2tf32(v.z); d[3] = f2tf32(v.w);
        }
        __syncthreads();

#pragma unroll
        for (int ks = 0; ks < 4; ks++) {
            const int kb = ks * 8;
            uint32_t af[4][4], bf[4][2];
#pragma unroll
            for (int mf = 0; mf < 4; mf++) {
                const uint32_t* ap = &As[(warp_m + mf * 16 + g) * APAD + kb + t];
                af[mf][0] = ap[0];
                af[mf][1] = ap[8 * APAD];
                af[mf][2] = ap[4];
                af[mf][3] = ap[8 * APAD + 4];
            }
#pragma unroll
            for (int nf = 0; nf < 4; nf++) {
                const uint32_t* bp = &Bs[(kb + t) * BPAD + warp_n + nf * 8 + g];
                bf[nf][0] = bp[0];
                bf[nf][1] = bp[4 * BPAD];
            }
#pragma unroll
            for (int mf = 0; mf < 4; mf++)
#pragma unroll
                for (int nf = 0; nf < 4; nf++)
                    mma_tf32(acc[mf][nf], af[mf], bf[nf]);
        }
    }

#pragma unroll
    for (int mf = 0; mf < 4; mf++) {
#pragma unroll
        for (int nf = 0; nf < 4; nf++) {
            const int n = bn + warp_n + nf * 8 + 2 * t;
            const float b0v = bias[n], b1v = bias[n + 1];
#pragma unroll
            for (int half = 0; half < 2; half++) {
                const int m = bm + warp_m + mf * 16 + g + half * 8;
                float v0 = acc[mf][nf][half * 2 + 0] + b0v;
                float v1 = acc[mf][nf][half * 2 + 1] + b1v;
                if (MODE == 0) {
                    int which = n >> 10;
                    int rem = n & 1023;
                    int h = rem >> 6, d = rem & 63;
                    int bi = m >> 11, tt = m & (T_ - 1);
                    float* dst = (which == 0) ? g_q : (which == 1) ? g_k : g_v;
                    *(float2*)&dst[(size_t)(((bi << 4) + h) * T_ + tt) * D_ + d] =
                        make_float2(v0, v1);
                } else {
                    *(float2*)&Out[(size_t)m * N + n] = make_float2(v0, v1);
                }
            }
        }
    }
}

// ===========================================================================
// tf32 mma.sync flash attention.
// CTA = (bh, 128 q-rows), 256 thr = 8 warps x 16 q-rows. K-tile 64.
// Q pre-scaled by 1/8 (exact pow2). D=64 => rows are 64 words:
//   Qs/Ks row stride 68 words (68%32=4): frag read bank = (4g+t+c)%32,
//     all 32 lanes distinct -> conflict-free.
//   Vs row stride 72 words (72%32=8): PV B-frag bank = (8t+g+c)%32,
//     all 32 lanes distinct -> conflict-free.
// Total dynamic smem = (128*68 + 64*68 + 64*72)*4 = 70656 B; 2 CTA/SM.
// ===========================================================================
#define QK_PAD 68
#define V_PAD  72
#define ATTN_SMEM_BYTES ((128 * QK_PAD + 64 * QK_PAD + 64 * V_PAD) * 4)

__global__ __launch_bounds__(256, 2) void attn_mma() {
    extern __shared__ uint32_t smu[];
    uint32_t* Qs = smu;                          // [128][68]
    uint32_t* Ks = smu + 128 * QK_PAD;           // [64][68]
    uint32_t* Vs = smu + 128 * QK_PAD + 64 * QK_PAD;  // [64][72]

    const int tid = threadIdx.x;
    const int wid = tid >> 5, lane = tid & 31;
    const int g = lane >> 2, t = lane & 3;
    const int bh = blockIdx.y;
    const int q0 = blockIdx.x * 128;
    const int qrow = wid * 16;              // warp's q-row base within tile

    const float* Qg = g_q + (size_t)bh * T_ * D_;
    const float* Kg = g_k + (size_t)bh * T_ * D_;
    const float* Vg = g_v + (size_t)bh * T_ * D_;

    // Load Q tile (scaled by 1/8, tf32). 128x64 floats, coalesced LDG.128.
#pragma unroll
    for (int r = 0; r < 8; r++) {
        int idx = tid + r * 256;
        int m = idx >> 4, c4 = idx & 15;
        float4 v = *(const float4*)(Qg + (size_t)(q0 + m) * D_ + c4 * 4);
        uint4 u = make_uint4(f2tf32(v.x * 0.125f), f2tf32(v.y * 0.125f),
                             f2tf32(v.z * 0.125f), f2tf32(v.w * 0.125f));
        *(uint4*)&Qs[m * QK_PAD + c4 * 4] = u;
    }

    float m_i[2] = {-1e30f, -1e30f};
    float l_i[2] = {0.f, 0.f};
    float o[8][4];
#pragma unroll
    for (int nb = 0; nb < 8; nb++)
#pragma unroll
        for (int r = 0; r < 4; r++) o[nb][r] = 0.f;

    for (int kt = 0; kt < T_; kt += 64) {
        __syncthreads();   // prior tile consumed (and Q visible on iter 0)

        // Load K,V tiles 64x64 each (tf32).
#pragma unroll
        for (int r = 0; r < 4; r++) {
            int idx = tid + r * 256;
            int s = idx >> 4, c4 = idx & 15;
            float4 v = *(const float4*)(Kg + (size_t)(kt + s) * D_ + c4 * 4);
            *(uint4*)&Ks[s * QK_PAD + c4 * 4] =
                make_uint4(f2tf32(v.x), f2tf32(v.y), f2tf32(v.z), f2tf32(v.w));
        }
#pragma unroll
        for (int r = 0; r < 4; r++) {
            int idx = tid + r * 256;
            int s = idx >> 4, c4 = idx & 15;
            float4 v = *(const float4*)(Vg + (size_t)(kt + s) * D_ + c4 * 4);
            *(uint4*)&Vs[s * V_PAD + c4 * 4] =
                make_uint4(f2tf32(v.x), f2tf32(v.y), f2tf32(v.z), f2tf32(v.w));
        }
        __syncthreads();

        // S = (Q/8) @ K^T : warp computes 16x64 -> 8 n8 fragment blocks.
        float sfr[8][4];
#pragma unroll
        for (int nb = 0; nb < 8; nb++)
#pragma unroll
            for (int r = 0; r < 4; r++) sfr[nb][r] = 0.f;

#pragma unroll
        for (int ks = 0; ks < 8; ks++) {
            uint32_t af[4];
            const uint32_t* ap = &Qs[(qrow + g) * QK_PAD + ks * 8 + t];
            af[0] = ap[0];
            af[1] = ap[8 * QK_PAD];
            af[2] = ap[4];
            af[3] = ap[8 * QK_PAD + 4];
#pragma unroll
            for (int nb = 0; nb < 8; nb++) {
                uint32_t bf[2];
                const uint32_t* bp = &Ks[(nb * 8 + g) * QK_PAD + ks * 8 + t];
                bf[0] = bp[0];
                bf[1] = bp[4];
                mma_tf32(sfr[nb], af, bf);
            }
        }

        // Online softmax per row-half (rows g and g+8), in-place exp on sfr.
#pragma unroll
        for (int half = 0; half < 2; half++) {
            const int h2 = half * 2;
            float mx = sfr[0][h2];
#pragma unroll
            for (int nb = 0; nb < 8; nb++) {
                mx = fmaxf(mx, sfr[nb][h2]);
                mx = fmaxf(mx, sfr[nb][h2 + 1]);
            }
            mx = fmaxf(mx, __shfl_xor_sync(0xffffffffu, mx, 1));
            mx = fmaxf(mx, __shfl_xor_sync(0xffffffffu, mx, 2));
            float mnew = fmaxf(m_i[half], mx);
            float corr = __expf(m_i[half] - mnew);
            m_i[half] = mnew;
            float ps = 0.f;
#pragma unroll
            for (int nb = 0; nb < 8; nb++) {
                float p0 = __expf(sfr[nb][h2] - mnew);
                float p1 = __expf(sfr[nb][h2 + 1] - mnew);
                sfr[nb][h2] = p0;
                sfr[nb][h2 + 1] = p1;
                ps += p0 + p1;
            }
            ps += __shfl_xor_sync(0xffffffffu, ps, 1);
            ps += __shfl_xor_sync(0xffffffffu, ps, 2);
            l_i[half] = l_i[half] * corr + ps;
#pragma unroll
            for (int nb = 0; nb < 8; nb++) {
                o[nb][h2] *= corr;
                o[nb][h2 + 1] *= corr;
            }
        }

        // O += P @ V. k-chunk ks (s = 8ks..8ks+7) uses P block sfr[ks].
        const int src0 = (lane & ~3) | (t >> 1);
#pragma unroll
        for (int ks = 0; ks < 8; ks++) {
            // P c-layout (cols 2t,2t+1) -> A-frag layout (cols t, t+4)
            float x00 = __shfl_sync(0xffffffffu, sfr[ks][0], src0);
            float x01 = __shfl_sync(0xffffffffu, sfr[ks][1], src0);
            float x20 = __shfl_sync(0xffffffffu, sfr[ks][0], src0 + 2);
            float x21 = __shfl_sync(0xffffffffu, sfr[ks][1], src0 + 2);
            float x10 = __shfl_sync(0xffffffffu, sfr[ks][2], src0);
            float x11 = __shfl_sync(0xffffffffu, sfr[ks][3], src0);
            float x30 = __shfl_sync(0xffffffffu, sfr[ks][2], src0 + 2);
            float x31 = __shfl_sync(0xffffffffu, sfr[ks][3], src0 + 2);
            uint32_t af[4];
            af[0] = f2tf32((t & 1) ? x01 : x00);
            af[1] = f2tf32((t & 1) ? x11 : x10);
            af[2] = f2tf32((t & 1) ? x21 : x20);
            af[3] = f2tf32((t & 1) ? x31 : x30);
#pragma unroll
            for (int db = 0; db < 8; db++) {
                uint32_t bf[2];
                const uint32_t* bp = &Vs[(ks * 8 + t) * V_PAD + db * 8 + g];
                bf[0] = bp[0];
                bf[1] = bp[4 * V_PAD];
                mma_tf32(o[db], af, bf);
            }
        }
    }

    // Normalize and write ctx[b][t][h*64+d]
    const int bi = bh >> 4, h = bh & 15;
    const float inv0 = 1.0f / l_i[0];
    const float inv1 = 1.0f / l_i[1];
#pragma unroll
    for (int db = 0; db < 8; db++) {
        const int d = db * 8 + 2 * t;
#pragma unroll
        for (int half = 0; half < 2; half++) {
            const float inv = half ? inv1 : inv0;
            const int tq = q0 + qrow + g + half * 8;
            float* dst = g_ctx + (size_t)(bi * T_ + tq) * C_ + h * D_ + d;
            *(float2*)dst = make_float2(o[db][half * 2] * inv,
                                        o[db][half * 2 + 1] * inv);
        }
    }
}

// ---------------------------------------------------------------------------
// Launch
// ---------------------------------------------------------------------------
extern "C" void kernel_launch(void* const* d_in, const int* in_sizes, int n_in,
                              void* d_out, int out_size) {
    const float* x     = (const float*)d_in[0];
    const float* W_qkv = (const float*)d_in[1];
    const float* b_qkv = (const float*)d_in[2];
    const float* W_out = (const float*)d_in[3];
    const float* b_out = (const float*)d_in[4];
    float* out = (float*)d_out;

    (void)in_sizes; (void)n_in; (void)out_size;

    cudaFuncSetAttribute(attn_mma, cudaFuncAttributeMaxDynamicSharedMemorySize,
                         ATTN_SMEM_BYTES);

    mma_gemm<0><<<dim3(3 * C_ / 128, M_ / 128), 256>>>(x, W_qkv, b_qkv,
                                                       nullptr, 3 * C_);
    attn_mma<<<dim3(T_ / 128, BH_), 256, ATTN_SMEM_BYTES>>>();
    mma_gemm<1><<<dim3(C_ / 128, M_ / 128), 256>>>(nullptr, W_out, b_out,
                                                   out, C_);
}